// round 4
// baseline (speedup 1.0000x reference)
#include <cuda_runtime.h>

// Problem constants: B=4, L=1024, E=256, S=32, W=2S+1=65
#define BB 4
#define LL 1024
#define EE 256
#define NEGF (-1e30f)
#define LOG2E 1.4426950408889634f

// Scratch for projected Q, K, V (4 MB each) — __device__ globals per allocation rules.
__device__ float g_Q[BB * LL * EE];
__device__ float g_K[BB * LL * EE];
__device__ float g_V[BB * LL * EE];

// ---------------------------------------------------------------------------
// helpers
// ---------------------------------------------------------------------------
__device__ __forceinline__ float ex2f(float x) {
    float r; asm("ex2.approx.f32 %0, %1;" : "=f"(r) : "f"(x)); return r;
}
__device__ __forceinline__ float rcpf(float x) {
    float r; asm("rcp.approx.f32 %0, %1;" : "=f"(r) : "f"(x)); return r;
}
__device__ __forceinline__ unsigned long long pack2(float x) {
    unsigned long long r; unsigned u = __float_as_uint(x);
    asm("mov.b64 %0, {%1, %1};" : "=l"(r) : "r"(u)); return r;
}
__device__ __forceinline__ void ffma2(unsigned long long& d,
                                      unsigned long long a, unsigned long long b) {
    // packed 2x fp32 FMA (full-rate fp32 path on sm_103a)
    asm("fma.rn.f32x2 %0, %1, %2, %0;" : "+l"(d) : "l"(a), "l"(b));
}
__device__ __forceinline__ float2 unpack2(unsigned long long v) {
    unsigned lo, hi;
    asm("mov.b64 {%0, %1}, %2;" : "=r"(lo), "=r"(hi) : "l"(v));
    return make_float2(__uint_as_float(lo), __uint_as_float(hi));
}

// ---------------------------------------------------------------------------
// Kernel 1: fused QKV projection.  out[m][n] = sum_k A[m][k] * W[n][k] + b[n]
// BM=128, BN=64, BK=16, 256 threads; per thread TM=8 (4 m-pairs) x TN=4.
// Inner loop: 4x LDS.128 + 16x FFMA2 (32 MACs).
// grid = (4096/128, 256/64, 3)  z selects (Wq,bq,g_Q)/(Wk,bk,g_K)/(Wv,bv,g_V)
// ---------------------------------------------------------------------------
__global__ __launch_bounds__(256) void qkv_gemm(
    const float* __restrict__ A,
    const float* __restrict__ W0, const float* __restrict__ b0,
    const float* __restrict__ W1, const float* __restrict__ b1,
    const float* __restrict__ W2, const float* __restrict__ b2)
{
    __shared__ __align__(16) float As[16][132];                  // [k][m], pad 4
    __shared__ __align__(16) unsigned long long Bs[16][66];      // [k][n], value duplicated in both lanes

    const int z = blockIdx.z;
    const float* Wm   = (z == 0) ? W0 : (z == 1) ? W1 : W2;
    const float* bias = (z == 0) ? b0 : (z == 1) ? b1 : b2;
    float*       out  = (z == 0) ? g_Q : (z == 1) ? g_K : g_V;

    const int tid = threadIdx.x;
    const int tx  = tid & 15;    // n group (4 cols)
    const int ty  = tid >> 4;    // m group (8 rows)
    const int m0  = blockIdx.x * 128;
    const int n0  = blockIdx.y * 64;

    const int la_m = tid >> 2;           // 0..63
    const int la_k = (tid & 3) << 2;     // 0,4,8,12
    const int lb_n = tid >> 2;
    const int lb_k = (tid & 3) << 2;

    unsigned long long acc[4][4];
    #pragma unroll
    for (int i2 = 0; i2 < 4; ++i2)
        #pragma unroll
        for (int j2 = 0; j2 < 4; ++j2) acc[i2][j2] = 0ull;

    for (int kt = 0; kt < 16; ++kt) {
        const int k0 = kt * 16;
        // stage global loads in registers
        float4 av0 = *(const float4*)&A [(m0 +      la_m) * EE + k0 + la_k];
        float4 av1 = *(const float4*)&A [(m0 + 64 + la_m) * EE + k0 + la_k];
        float4 wv  = *(const float4*)&Wm[(n0 +      lb_n) * EE + k0 + lb_k];

        __syncthreads();   // previous tile fully consumed
        As[la_k + 0][la_m] = av0.x; As[la_k + 1][la_m] = av0.y;
        As[la_k + 2][la_m] = av0.z; As[la_k + 3][la_m] = av0.w;
        As[la_k + 0][64 + la_m] = av1.x; As[la_k + 1][64 + la_m] = av1.y;
        As[la_k + 2][64 + la_m] = av1.z; As[la_k + 3][64 + la_m] = av1.w;
        Bs[lb_k + 0][lb_n] = pack2(wv.x); Bs[lb_k + 1][lb_n] = pack2(wv.y);
        Bs[lb_k + 2][lb_n] = pack2(wv.z); Bs[lb_k + 3][lb_n] = pack2(wv.w);
        __syncthreads();

        #pragma unroll
        for (int kk = 0; kk < 16; ++kk) {
            ulonglong2 a01 = *(const ulonglong2*)&As[kk][ty * 8];
            ulonglong2 a23 = *(const ulonglong2*)&As[kk][ty * 8 + 4];
            ulonglong2 bq0 = *(const ulonglong2*)&Bs[kk][tx * 4];
            ulonglong2 bq1 = *(const ulonglong2*)&Bs[kk][tx * 4 + 2];
            unsigned long long am[4] = {a01.x, a01.y, a23.x, a23.y};
            unsigned long long bn[4] = {bq0.x, bq0.y, bq1.x, bq1.y};
            #pragma unroll
            for (int i2 = 0; i2 < 4; ++i2)
                #pragma unroll
                for (int j2 = 0; j2 < 4; ++j2)
                    ffma2(acc[i2][j2], am[i2], bn[j2]);
        }
    }

    float4 bv4 = *(const float4*)&bias[n0 + tx * 4];
    const float bb[4] = {bv4.x, bv4.y, bv4.z, bv4.w};
    #pragma unroll
    for (int i2 = 0; i2 < 4; ++i2) {
        const int m = m0 + ty * 8 + i2 * 2;
        float2 u0 = unpack2(acc[i2][0]);
        float2 u1 = unpack2(acc[i2][1]);
        float2 u2 = unpack2(acc[i2][2]);
        float2 u3 = unpack2(acc[i2][3]);
        float4 r0 = make_float4(u0.x + bb[0], u1.x + bb[1], u2.x + bb[2], u3.x + bb[3]);
        float4 r1 = make_float4(u0.y + bb[0], u1.y + bb[1], u2.y + bb[2], u3.y + bb[3]);
        *(float4*)&out[(m    ) * EE + n0 + tx * 4] = r0;
        *(float4*)&out[(m + 1) * EE + n0 + tx * 4] = r1;
    }
}

// ---------------------------------------------------------------------------
// Kernel 2: AFT-local attention (per-channel softmax over 65-wide window).
// Block = 256 threads, covers 64 i-rows x 64 e-channels.
// smem: K,V tiles of 128 rows (64 + 2S halo, zero-filled OOB) x 64 channels.
// pos_bias column for the thread's channel lives in 65 registers.
// Unshifted softmax (max|logit| << 80, provably no fp32 overflow).
// ---------------------------------------------------------------------------
template <bool CHECK>
__device__ __forceinline__ void aft_one_row(
    int i, int il, int c, int bi, int e,
    const float* __restrict__ Ks, const float* __restrict__ Vs,
    const float* __restrict__ pb, float* __restrict__ out)
{
    const float qv = g_Q[(bi * LL + i) * EE + e];
    const float qs = qv * LOG2E;               // fold log2(e) for ex2.approx
    float den = 0.0f, num = 0.0f;
    #pragma unroll
    for (int w = 0; w <= 64; ++w) {
        const int r = (il + w) * 64 + c;       // smem tile row: (i - i0) + w
        float p;
        if (w == 0 || w == 64) {
            // |rel| == S -> K masked to 0 -> logit 0 (valid) / -inf (invalid)
            if (CHECK) {
                const bool v = (unsigned)(i + w - 32) < (unsigned)LL;
                p = v ? 1.0f : 0.0f;
            } else {
                p = 1.0f;
            }
        } else {
            float l = qs * (Ks[r] + pb[w]);    // log2-domain logit
            if (CHECK) {
                const bool v = (unsigned)(i + w - 32) < (unsigned)LL;
                l = v ? l : NEGF;
            }
            p = ex2f(l);
        }
        den += p;
        num = fmaf(p, Vs[r], num);             // Vs zero-filled OOB
    }
    const float s = rcpf(1.0f + ex2f(-qs));    // sigmoid(qv)
    out[(bi * LL + i) * EE + e] = s * s * num * rcpf(den);
}

__global__ __launch_bounds__(256) void aft_local(
    const float* __restrict__ pos_bias,   // [65][256]
    float* __restrict__ out)              // [B][L][E]
{
    extern __shared__ float smem[];
    float* Ks = smem;                 // [128][64]
    float* Vs = smem + 128 * 64;      // [128][64]

    const int tid = threadIdx.x;
    const int c   = tid & 63;         // channel within block
    const int ig  = tid >> 6;         // 0..3 (i interleave group)
    const int e0  = blockIdx.x * 64;
    const int i0  = blockIdx.y * 64;
    const int bi  = blockIdx.z;
    const int e   = e0 + c;
    const int j0  = i0 - 32;

    // Load K/V tile rows [i0-32, i0+95], zero-fill out-of-sequence rows.
    for (int idx = tid; idx < 128 * 16; idx += 256) {
        const int r  = idx >> 4;
        const int cc = (idx & 15) << 2;
        const int j  = j0 + r;
        float4 kv = make_float4(0.f, 0.f, 0.f, 0.f);
        float4 vv = make_float4(0.f, 0.f, 0.f, 0.f);
        if ((unsigned)j < (unsigned)LL) {
            const int off = (bi * LL + j) * EE + e0 + cc;
            kv = *(const float4*)&g_K[off];
            vv = *(const float4*)&g_V[off];
        }
        *(float4*)&Ks[r * 64 + cc] = kv;
        *(float4*)&Vs[r * 64 + cc] = vv;
    }

    // pos_bias column for this thread's channel -> 65 registers (coalesced loads)
    float pb[65];
    #pragma unroll
    for (int w = 0; w <= 64; ++w) pb[w] = pos_bias[w * EE + e];

    __syncthreads();

    const bool interior = (i0 >= 32) && (i0 + 96 <= LL);
    if (interior) {
        #pragma unroll 1
        for (int ii = 0; ii < 16; ++ii) {
            const int il = ii * 4 + ig;
            aft_one_row<false>(i0 + il, il, c, bi, e, Ks, Vs, pb, out);
        }
    } else {
        #pragma unroll 1
        for (int ii = 0; ii < 16; ++ii) {
            const int il = ii * 4 + ig;
            aft_one_row<true>(i0 + il, il, c, bi, e, Ks, Vs, pb, out);
        }
    }
}

// ---------------------------------------------------------------------------
// launch
// ---------------------------------------------------------------------------
extern "C" void kernel_launch(void* const* d_in, const int* in_sizes, int n_in,
                              void* d_out, int out_size)
{
    const float* q  = (const float*)d_in[0];
    const float* Wq = (const float*)d_in[1];
    const float* bq = (const float*)d_in[2];
    const float* Wk = (const float*)d_in[3];
    const float* bk = (const float*)d_in[4];
    const float* Wv = (const float*)d_in[5];
    const float* bv = (const float*)d_in[6];
    const float* pb = (const float*)d_in[7];
    float* out = (float*)d_out;

    (void)in_sizes; (void)n_in; (void)out_size;

    dim3 gg(4096 / 128, 256 / 64, 3);
    qkv_gemm<<<gg, 256>>>(q, Wq, bq, Wk, bk, Wv, bv);

    // 64 KB dynamic smem (> 48 KB default) — idempotent, capture-safe
    cudaFuncSetAttribute(aft_local, cudaFuncAttributeMaxDynamicSharedMemorySize, 65536);
    dim3 ga(EE / 64, LL / 64, BB);
    aft_local<<<ga, 256, 65536>>>(pb, out);
}

// round 5
// speedup vs baseline: 1.8782x; 1.8782x over previous
#include <cuda_runtime.h>
#include <cuda_bf16.h>

// Problem constants: B=4, L=1024, E=256, S=32, W=2S+1=65
#define BB 4
#define LL 1024
#define EE 256
#define LOG2E 1.4426950408889634f

// ---------------------------------------------------------------------------
// Device-global scratch (no allocations allowed)
// ---------------------------------------------------------------------------
__device__ float g_Q[BB * LL * EE];
__device__ float g_K[BB * LL * EE];
__device__ float g_V[BB * LL * EE];
__device__ __nv_bfloat16 g_Ah[BB * LL * EE];     // input A split hi
__device__ __nv_bfloat16 g_Al[BB * LL * EE];     // input A split lo
__device__ __nv_bfloat16 g_Wh[3 * EE * EE];      // Wq|Wk|Wv split hi
__device__ __nv_bfloat16 g_Wl[3 * EE * EE];      // Wq|Wk|Wv split lo

// ---------------------------------------------------------------------------
// helpers
// ---------------------------------------------------------------------------
__device__ __forceinline__ float ex2f(float x) {
    float r; asm("ex2.approx.f32 %0, %1;" : "=f"(r) : "f"(x)); return r;
}
__device__ __forceinline__ float rcpf(float x) {
    float r; asm("rcp.approx.f32 %0, %1;" : "=f"(r) : "f"(x)); return r;
}
__device__ __forceinline__ void ldsm4(unsigned* r, unsigned addr) {
    asm volatile("ldmatrix.sync.aligned.m8n8.x4.shared.b16 {%0,%1,%2,%3}, [%4];"
                 : "=r"(r[0]), "=r"(r[1]), "=r"(r[2]), "=r"(r[3]) : "r"(addr));
}
__device__ __forceinline__ void mma16816(float* c, const unsigned* a, const unsigned* b) {
    asm volatile(
        "mma.sync.aligned.m16n8k16.row.col.f32.bf16.bf16.f32 "
        "{%0,%1,%2,%3},{%4,%5,%6,%7},{%8,%9},{%0,%1,%2,%3};"
        : "+f"(c[0]), "+f"(c[1]), "+f"(c[2]), "+f"(c[3])
        : "r"(a[0]), "r"(a[1]), "r"(a[2]), "r"(a[3]), "r"(b[0]), "r"(b[1]));
}

// ---------------------------------------------------------------------------
// Kernel 0: split fp32 -> bf16 (hi) + bf16 (residual lo) for A and the 3 W's.
// Exact grid: (NA + 3*NW)/4 float4 elements, 1216 blocks x 256 threads.
// ---------------------------------------------------------------------------
#define NA (BB * LL * EE)   // 1048576
#define NW (EE * EE)        // 65536

__global__ __launch_bounds__(256) void cvt_split(
    const float* __restrict__ A,
    const float* __restrict__ W0, const float* __restrict__ W1,
    const float* __restrict__ W2)
{
    const int i4 = blockIdx.x * 256 + threadIdx.x;
    const int A4 = NA / 4;     // 262144
    const int W4 = NW / 4;     // 16384
    const float* src;
    __nv_bfloat16 *dh, *dl;
    int off;
    if (i4 < A4) {
        src = A; dh = g_Ah; dl = g_Al; off = i4;
    } else {
        int r = i4 - A4;
        int z = r / W4;
        off = r - z * W4;
        src = (z == 0) ? W0 : (z == 1) ? W1 : W2;
        dh = g_Wh + z * NW; dl = g_Wl + z * NW;
    }
    float4 x = ((const float4*)src)[off];
    float xs[4] = {x.x, x.y, x.z, x.w};
    __nv_bfloat16 h[4], l[4];
    #pragma unroll
    for (int j = 0; j < 4; ++j) {
        h[j] = __float2bfloat16(xs[j]);
        l[j] = __float2bfloat16(xs[j] - __bfloat162float(h[j]));
    }
    *(uint2*)&dh[off * 4] = *(uint2*)h;
    *(uint2*)&dl[off * 4] = *(uint2*)l;
}

// ---------------------------------------------------------------------------
// Kernel 1: QKV projection via tensor cores (bf16 3-term split).
// out[m][n] = sum_k A[m][k]*W[n][k] + bias[n]
// Block: 256 thr (8 warps, 4x2), BM=128, BN=64, BK=32.
// smem tiles pitch 40 bf16 (80B) -> conflict-free ldmatrix.
// grid = (32, 4, 3); z selects (Wq,bq,g_Q)/(Wk,bk,g_K)/(Wv,bv,g_V).
// ---------------------------------------------------------------------------
__global__ __launch_bounds__(256, 2) void qkv_mma(
    const float* __restrict__ bq, const float* __restrict__ bk,
    const float* __restrict__ bv)
{
    __shared__ __align__(16) __nv_bfloat16 sA[2][128 * 40];  // [hi/lo][row][k] pitch 40
    __shared__ __align__(16) __nv_bfloat16 sW[2][64 * 40];

    const int tid = threadIdx.x;
    const int z = blockIdx.z;
    const int m0 = blockIdx.x * 128;
    const int n0 = blockIdx.y * 64;
    const __nv_bfloat16* gWh = g_Wh + z * NW;
    const __nv_bfloat16* gWl = g_Wl + z * NW;

    const int lane = tid & 31, wid = tid >> 5;
    const int wm = wid & 3;        // warp row block (32 rows)
    const int wn = wid >> 2;       // warp col block (32 cols)

    const int lr = tid >> 2;             // 0..63
    const int lk = (tid & 3) * 8;        // 0,8,16,24 (bf16 elems)

    float acc[2][4][4];
    #pragma unroll
    for (int mt = 0; mt < 2; ++mt)
        #pragma unroll
        for (int nt = 0; nt < 4; ++nt)
            #pragma unroll
            for (int r = 0; r < 4; ++r) acc[mt][nt][r] = 0.0f;

    // ldmatrix lane addressing (computed once)
    const int mat = lane >> 3;
    const int a_m = (mat & 1) * 8 + (lane & 7);
    const int a_k = (mat >> 1) * 8;
    const int w_n = (mat >> 1) * 8 + (lane & 7);
    const int w_k = (mat & 1) * 8;

    for (int kt = 0; kt < 8; ++kt) {
        const int k0 = kt * 32;
        // stage global loads
        uint4 ah0 = *(const uint4*)&g_Ah[(m0 + lr) * EE + k0 + lk];
        uint4 ah1 = *(const uint4*)&g_Ah[(m0 + 64 + lr) * EE + k0 + lk];
        uint4 al0 = *(const uint4*)&g_Al[(m0 + lr) * EE + k0 + lk];
        uint4 al1 = *(const uint4*)&g_Al[(m0 + 64 + lr) * EE + k0 + lk];
        uint4 wh0 = *(const uint4*)&gWh[(n0 + lr) * EE + k0 + lk];
        uint4 wl0 = *(const uint4*)&gWl[(n0 + lr) * EE + k0 + lk];
        __syncthreads();
        *(uint4*)&sA[0][lr * 40 + lk] = ah0;
        *(uint4*)&sA[0][(64 + lr) * 40 + lk] = ah1;
        *(uint4*)&sA[1][lr * 40 + lk] = al0;
        *(uint4*)&sA[1][(64 + lr) * 40 + lk] = al1;
        *(uint4*)&sW[0][lr * 40 + lk] = wh0;
        *(uint4*)&sW[1][lr * 40 + lk] = wl0;
        __syncthreads();

        #pragma unroll
        for (int ks = 0; ks < 2; ++ks) {
            unsigned ah[2][4], al[2][4], bh[4][2], bl[4][2];
            #pragma unroll
            for (int mt = 0; mt < 2; ++mt) {
                unsigned adr_h = (unsigned)__cvta_generic_to_shared(
                    &sA[0][(wm * 32 + mt * 16 + a_m) * 40 + ks * 16 + a_k]);
                unsigned adr_l = (unsigned)__cvta_generic_to_shared(
                    &sA[1][(wm * 32 + mt * 16 + a_m) * 40 + ks * 16 + a_k]);
                ldsm4(ah[mt], adr_h);
                ldsm4(al[mt], adr_l);
            }
            #pragma unroll
            for (int np = 0; np < 2; ++np) {
                unsigned t[4];
                unsigned adr_h = (unsigned)__cvta_generic_to_shared(
                    &sW[0][(wn * 32 + np * 16 + w_n) * 40 + ks * 16 + w_k]);
                ldsm4(t, adr_h);
                bh[np * 2][0] = t[0]; bh[np * 2][1] = t[1];
                bh[np * 2 + 1][0] = t[2]; bh[np * 2 + 1][1] = t[3];
                unsigned adr_l = (unsigned)__cvta_generic_to_shared(
                    &sW[1][(wn * 32 + np * 16 + w_n) * 40 + ks * 16 + w_k]);
                ldsm4(t, adr_l);
                bl[np * 2][0] = t[0]; bl[np * 2][1] = t[1];
                bl[np * 2 + 1][0] = t[2]; bl[np * 2 + 1][1] = t[3];
            }
            #pragma unroll
            for (int mt = 0; mt < 2; ++mt)
                #pragma unroll
                for (int nt = 0; nt < 4; ++nt) {
                    mma16816(acc[mt][nt], ah[mt], bh[nt]);   // hi*hi
                    mma16816(acc[mt][nt], ah[mt], bl[nt]);   // hi*lo
                    mma16816(acc[mt][nt], al[mt], bh[nt]);   // lo*hi
                }
        }
    }

    // epilogue: + bias, write fp32
    float* out = (z == 0) ? g_Q : (z == 1) ? g_K : g_V;
    const float* bias = (z == 0) ? bq : (z == 1) ? bk : bv;
    #pragma unroll
    for (int nt = 0; nt < 4; ++nt) {
        const int n = n0 + wn * 32 + nt * 8 + (lane & 3) * 2;
        const float b0 = bias[n], b1 = bias[n + 1];
        #pragma unroll
        for (int mt = 0; mt < 2; ++mt) {
            const int m = m0 + wm * 32 + mt * 16 + (lane >> 2);
            float2 r0 = make_float2(acc[mt][nt][0] + b0, acc[mt][nt][1] + b1);
            float2 r1 = make_float2(acc[mt][nt][2] + b0, acc[mt][nt][3] + b1);
            *(float2*)&out[m * EE + n] = r0;
            *(float2*)&out[(m + 8) * EE + n] = r1;
        }
    }
}

// ---------------------------------------------------------------------------
// Kernel 2: AFT-local attention. Per-channel softmax over 65-wide window.
// Block: 256 thr, tile 64 rows x 64 channels; K/V smem tiles 128 rows
// (64 + 2S halo, zero-filled OOB). Each thread processes 4 CONSECUTIVE rows
// per pass so each K/V smem value is loaded once and reused 4x.
// pos_bias[1..63] for the thread's channel in registers (w=0,64 -> p=1).
// Unshifted softmax (|log2 logits| < ~40, no fp32 overflow possible).
// ---------------------------------------------------------------------------
template <bool CHECK>
__device__ __forceinline__ void aft_rows(
    int i0, int j0, int c, int bi, int e, int rg,
    const float* __restrict__ Ks, const float* __restrict__ Vs,
    const float* __restrict__ pb, float* __restrict__ out)
{
    #pragma unroll 1
    for (int pass = 0; pass < 4; ++pass) {
        const int il = pass * 16 + rg * 4;   // 4 consecutive rows il..il+3
        float qs[4], den[4], num[4];
        #pragma unroll
        for (int d = 0; d < 4; ++d) {
            const float qv = g_Q[(bi * LL + i0 + il + d) * EE + e];
            qs[d] = qv * LOG2E;
            float v0 = 1.0f, v64 = 1.0f;
            if (CHECK) {
                v0  = ((unsigned)(j0 + il + d)      < (unsigned)LL) ? 1.0f : 0.0f;
                v64 = ((unsigned)(j0 + il + d + 64) < (unsigned)LL) ? 1.0f : 0.0f;
            }
            den[d] = v0 + v64;                               // w=0, w=64: p = 1 (K masked to 0)
            num[d] = Vs[(il + d) * 64 + c] + Vs[(il + d + 64) * 64 + c];  // V zero-filled OOB
        }
        #pragma unroll
        for (int jo = 1; jo <= 66; ++jo) {
            const int r = (il + jo) * 64 + c;
            const float k = Ks[r];
            const float v = Vs[r];
            float vj = 1.0f;
            if (CHECK) vj = ((unsigned)(j0 + il + jo) < (unsigned)LL) ? 1.0f : 0.0f;
            #pragma unroll
            for (int d = 0; d < 4; ++d) {
                const int w = jo - d;        // compile-time
                if (w >= 1 && w <= 63) {
                    float l = qs[d] * (k + pb[w]);   // log2-domain logit
                    float p = ex2f(l);
                    if (CHECK) p *= vj;
                    den[d] += p;
                    num[d] = fmaf(p, v, num[d]);
                }
            }
        }
        #pragma unroll
        for (int d = 0; d < 4; ++d) {
            const float s = rcpf(1.0f + ex2f(-qs[d]));       // sigmoid(qv)
            out[(bi * LL + i0 + il + d) * EE + e] = s * s * num[d] * rcpf(den[d]);
        }
    }
}

__global__ __launch_bounds__(256) void aft_local(
    const float* __restrict__ pos_bias,   // [65][256]
    float* __restrict__ out)              // [B][L][E]
{
    extern __shared__ float smem[];
    float* Ks = smem;                 // [128][64]
    float* Vs = smem + 128 * 64;      // [128][64]

    const int tid = threadIdx.x;
    const int c   = tid & 63;         // channel within block
    const int rg  = tid >> 6;         // row group 0..3 (uniform per warp)
    const int e0  = blockIdx.x * 64;
    const int i0  = blockIdx.y * 64;
    const int bi  = blockIdx.z;
    const int e   = e0 + c;
    const int j0  = i0 - 32;

    // Load K/V tile rows [i0-32, i0+95], zero-fill out-of-sequence rows.
    for (int idx = tid; idx < 128 * 16; idx += 256) {
        const int r  = idx >> 4;
        const int cc = (idx & 15) << 2;
        const int j  = j0 + r;
        float4 kv = make_float4(0.f, 0.f, 0.f, 0.f);
        float4 vv = make_float4(0.f, 0.f, 0.f, 0.f);
        if ((unsigned)j < (unsigned)LL) {
            const int off = (bi * LL + j) * EE + e0 + cc;
            kv = *(const float4*)&g_K[off];
            vv = *(const float4*)&g_V[off];
        }
        *(float4*)&Ks[r * 64 + cc] = kv;
        *(float4*)&Vs[r * 64 + cc] = vv;
    }

    // pos_bias column (w = 1..63 only; w=0/64 never read pb)
    float pb[64];
    #pragma unroll
    for (int w = 1; w < 64; ++w) pb[w] = pos_bias[w * EE + e];

    __syncthreads();

    const bool interior = (i0 >= 32) && (i0 + 96 <= LL);
    if (interior) aft_rows<false>(i0, j0, c, bi, e, rg, Ks, Vs, pb, out);
    else          aft_rows<true >(i0, j0, c, bi, e, rg, Ks, Vs, pb, out);
}

// ---------------------------------------------------------------------------
// launch
// ---------------------------------------------------------------------------
extern "C" void kernel_launch(void* const* d_in, const int* in_sizes, int n_in,
                              void* d_out, int out_size)
{
    const float* q  = (const float*)d_in[0];
    const float* Wq = (const float*)d_in[1];
    const float* bq = (const float*)d_in[2];
    const float* Wk = (const float*)d_in[3];
    const float* bk = (const float*)d_in[4];
    const float* Wv = (const float*)d_in[5];
    const float* bv = (const float*)d_in[6];
    const float* pb = (const float*)d_in[7];
    float* out = (float*)d_out;

    (void)in_sizes; (void)n_in; (void)out_size;

    // 0: fp32 -> bf16 hi/lo split of A and W's  (1216*256 threads covers all)
    cvt_split<<<1216, 256>>>(q, Wq, Wk, Wv);

    // 1: QKV projection on tensor cores
    dim3 gg(32, 4, 3);
    qkv_mma<<<gg, 256>>>(bq, bk, bv);

    // 2: AFT local attention (64 KB dynamic smem)
    cudaFuncSetAttribute(aft_local, cudaFuncAttributeMaxDynamicSharedMemorySize, 65536);
    dim3 ga(EE / 64, LL / 64, BB);
    aft_local<<<ga, 256, 65536>>>(pb, out);
}